// round 9
// baseline (speedup 1.0000x reference)
#include <cuda_runtime.h>
#include <cuda_bf16.h>

// Problem constants (fixed shapes from reference setup_inputs)
#define NB     307
#define SSUB   4
#define MTOT   (NB * SSUB)      // 1228 (even)
#define RHALF  614              // rows per parity slice
#define TT     12
#define BBAT   16
#define BT     (BBAT * TT)      // 192
#define CC     64
#define MAXE   64               // total entries per row (actual <= 44)
#define MAXP   48               // entries per (row,parity) (provably <= 42)
#define TMAIN  384
#define NWMAIN 12
#define NCHUNK 13               // ceil(154/12)
#define H0ROWS 154
#define H1ROWS 153
#define NUNITS (BT * 2 * 2)     // 768: (bt, parity, half)

#define EMB_B  (RHALF * CC * 2)        // 78,592
#define ABUF_B (2 * NWMAIN * CC * 4)   // 6,144 (double-buffered A chunk)
#define SMEM_MAIN (EMB_B + ABUF_B)     // 84,736 -> 2 CTAs/SM

#define NGROUPS (BBAT * NB * TT)       // 58944
#define NORM_BLOCKS 3684               // 58944/2 groups-per-warp / 8 warps
#define MASK_BLOCKS 39

// Scratch (static device allocations — no runtime alloc)
__device__ __nv_bfloat16 g_embT[(size_t)BT * 2 * RHALF * CC]; // [bt][par][r][c]
__device__ int           g_cnt2[NB * 2];
__device__ __align__(16) unsigned short g_pk2[NB * 2 * MAXP]; // r(10b)|pos<<11|dbl<<12
__device__ float         g_num[2 * BT * NB];                  // [par][bt][n]
__device__ float         g_den[2 * BT * NB];
__device__ float         g_partial[BT];
__device__ int           g_done;

__device__ __forceinline__ float bf_lo(unsigned u) { return __uint_as_float(u << 16); }
__device__ __forceinline__ float bf_hi(unsigned u) { return __uint_as_float(u & 0xffff0000u); }
__device__ __forceinline__ unsigned smem_u32(const void* p) {
    return (unsigned)__cvta_generic_to_shared(p);
}
__device__ __forceinline__ void cp16(unsigned dst, const void* src) {
    asm volatile("cp.async.cg.shared.global [%0], [%1], 16;" :: "r"(dst), "l"(src));
}

// ---------------------------------------------------------------------------
// Kernel 1: role A = normalize (2 groups per warp, MLP=4);
//           role B = masks with O(1) ballot-based bank dealing.
// ---------------------------------------------------------------------------
__global__ void k_prep(const float* __restrict__ se,
                       const float* __restrict__ pos,
                       const float* __restrict__ neg) {
    if (blockIdx.x < NORM_BLOCKS) {
        int warp = (blockIdx.x * blockDim.x + threadIdx.x) >> 5;
        int lane = threadIdx.x & 31;
        int g0 = 2 * warp, g1 = g0 + 1;   // two (b,j,t) groups per warp
        const float4* s0 = (const float4*)(se) + (size_t)g0 * CC;
        const float4* s1 = (const float4*)(se) + (size_t)g1 * CC;
        float4 a0 = s0[2 * lane], a1 = s0[2 * lane + 1];
        float4 b0 = s1[2 * lane], b1 = s1[2 * lane + 1];

        float p0 = a0.x * a0.x + a1.x * a1.x;
        float p1 = a0.y * a0.y + a1.y * a1.y;
        float p2 = a0.z * a0.z + a1.z * a1.z;
        float p3 = a0.w * a0.w + a1.w * a1.w;
        float q0 = b0.x * b0.x + b1.x * b1.x;
        float q1 = b0.y * b0.y + b1.y * b1.y;
        float q2 = b0.z * b0.z + b1.z * b1.z;
        float q3 = b0.w * b0.w + b1.w * b1.w;
        #pragma unroll
        for (int off = 16; off; off >>= 1) {
            p0 += __shfl_xor_sync(0xffffffffu, p0, off);
            p1 += __shfl_xor_sync(0xffffffffu, p1, off);
            p2 += __shfl_xor_sync(0xffffffffu, p2, off);
            p3 += __shfl_xor_sync(0xffffffffu, p3, off);
            q0 += __shfl_xor_sync(0xffffffffu, q0, off);
            q1 += __shfl_xor_sync(0xffffffffu, q1, off);
            q2 += __shfl_xor_sync(0xffffffffu, q2, off);
            q3 += __shfl_xor_sync(0xffffffffu, q3, off);
        }
        float sp[4] = { rsqrtf(fmaxf(p0, 1e-24f)), rsqrtf(fmaxf(p1, 1e-24f)),
                        rsqrtf(fmaxf(p2, 1e-24f)), rsqrtf(fmaxf(p3, 1e-24f)) };
        float sq[4] = { rsqrtf(fmaxf(q0, 1e-24f)), rsqrtf(fmaxf(q1, 1e-24f)),
                        rsqrtf(fmaxf(q2, 1e-24f)), rsqrtf(fmaxf(q3, 1e-24f)) };

        float lo0[4] = { a0.x, a0.y, a0.z, a0.w };
        float hi0[4] = { a1.x, a1.y, a1.z, a1.w };
        float lo1[4] = { b0.x, b0.y, b0.z, b0.w };
        float hi1[4] = { b1.x, b1.y, b1.z, b1.w };

        #pragma unroll
        for (int g = 0; g < 2; g++) {
            int gid = g ? g1 : g0;
            int t  = gid % TT;
            int bj = gid / TT;
            int j  = bj % NB;
            int bt = (bj / NB) * TT + t;
            #pragma unroll
            for (int s = 0; s < SSUB; s++) {
                int m = s * NB + j;
                float sc = g ? sq[s] : sp[s];
                float lo = (g ? lo1[s] : lo0[s]) * sc;
                float hi = (g ? hi1[s] : hi0[s]) * sc;
                __nv_bfloat162* dst = (__nv_bfloat162*)(g_embT
                    + (((size_t)(bt * 2 + (m & 1)) * RHALF + (m >> 1)) * CC)) + lane;
                *dst = __floats2bfloat162_rn(lo, hi);
            }
        }
    } else {
        // mask role: warp w handles n = (blk-NORM)*8 + w
        __shared__ unsigned short buf[8][MAXE];   // r | pos<<11 | dbl<<12 | par<<13
        int mb = blockIdx.x - NORM_BLOCKS;
        int wid = threadIdx.x >> 5, lane = threadIdx.x & 31;
        if (mb == 0 && threadIdx.x == 0) g_done = 0;
        int n = mb * 8 + wid;
        if (n >= NB) return;
        int base = 0;
        for (int m0 = 0; m0 < MTOT; m0 += 32) {
            int m = m0 + lane;
            float p = 0.0f, q = 0.0f;
            if (m < MTOT) {
                p = pos[(size_t)n * MTOT + m];
                q = neg[(size_t)n * MTOT + m];
            }
            float w = p + q;
            unsigned bal = __ballot_sync(0xffffffffu, w > 0.0f);
            if (w > 0.0f) {
                int i = base + __popc(bal & ((1u << lane) - 1u));
                if (i < MAXE) {
                    buf[wid][i] = (unsigned short)((m >> 1)
                        | ((p > 0.5f) ? 2048 : 0)
                        | ((w > 1.5f) ? 4096 : 0)
                        | ((m & 1) << 13));
                }
            }
            base += __popc(bal);
        }
        int cnt = min(base, MAXE);
        __syncwarp();
        unsigned e0 = (lane < cnt)      ? buf[wid][lane]      : 0xFFFFu;
        unsigned e1 = (lane + 32 < cnt) ? buf[wid][lane + 32] : 0xFFFFu;
        unsigned below = (1u << lane) - 1u;

        #pragma unroll
        for (int par = 0; par < 2; par++) {
            bool v0 = (e0 != 0xFFFFu) && (((e0 >> 13) & 1) == (unsigned)par);
            bool v1 = (e1 != 0xFFFFu) && (((e1 >> 13) & 1) == (unsigned)par);
            int bk0 = e0 & 7, bk1 = e1 & 7;
            unsigned bal0[8], bal1[8];
            int cntb[8], cntp = 0;
            #pragma unroll
            for (int k = 0; k < 8; k++) {
                bal0[k] = __ballot_sync(0xffffffffu, v0 && bk0 == k);
                bal1[k] = __ballot_sync(0xffffffffu, v1 && bk1 == k);
                cntb[k] = __popc(bal0[k]) + __popc(bal1[k]);
                cntp += cntb[k];
            }
            // closed-form dealt position: pos = sum_b min(cntb[b], rk + (b<bk))
            if (v0) {
                int rk = __popc(bal0[bk0] & below);
                int ps = 0;
                #pragma unroll
                for (int b2 = 0; b2 < 8; b2++)
                    ps += min(cntb[b2], rk + (b2 < bk0 ? 1 : 0));
                g_pk2[(n * 2 + par) * MAXP + ps] = (unsigned short)(e0 & 0x1FFF);
            }
            if (v1) {
                int rk = __popc(bal0[bk1]) + __popc(bal1[bk1] & below);
                int ps = 0;
                #pragma unroll
                for (int b2 = 0; b2 < 8; b2++)
                    ps += min(cntb[b2], rk + (b2 < bk1 ? 1 : 0));
                g_pk2[(n * 2 + par) * MAXP + ps] = (unsigned short)(e1 & 0x1FFF);
            }
            if (lane == 0) g_cnt2[n * 2 + par] = min(cntp, MAXP);
        }
    }
}

// ---------------------------------------------------------------------------
// Kernel 2: main SDDMM. 768 blocks = (bt, parity, half), 2 CTAs/SM.
// Per unit: cp.async-fill parity emb slice (swizzled); A-vectors software-
// pipelined through a 12-row double-buffered smem stage; pk/cnt prefetched
// one chunk ahead into regs. Hot loop: dealt conflict-free LDS.128, 8 FMA
// accumulators, per-row shfl-reduced num/den -> g_num/g_den (deterministic).
// ---------------------------------------------------------------------------
__global__ void __launch_bounds__(TMAIN, 2) k_main(const float* __restrict__ node_mem) {
    extern __shared__ __align__(16) char smraw[];
    uint4* semb = (uint4*)smraw;                 // RHALF*8 uint4, swizzled
    float* sA   = (float*)(smraw + EMB_B);       // 2 x 12 x 64 f32

    int u = blockIdx.x;
    int bt = u >> 2, parity = (u >> 1) & 1, half = u & 1;
    int b = bt / TT, t = bt % TT;
    int n0   = half ? H0ROWS : 0;
    int rows = half ? H1ROWS : H0ROWS;
    int wid = threadIdx.x >> 5, lane = threadIdx.x & 31;

    // emb fill (once per unit)
    {
        const uint4* esrc = (const uint4*)(g_embT) + (size_t)(bt * 2 + parity) * RHALF * 8;
        for (int idx = threadIdx.x; idx < RHALF * 8; idx += TMAIN) {
            int r = idx >> 3, w = idx & 7;
            cp16(smem_u32(&semb[(r << 3) | (w ^ (r & 7))]), esrc + idx);
        }
    }
    // stage A chunk 0
    {
        int nrow = min(NWMAIN, rows);
        for (int idx = threadIdx.x; idx < nrow * 16; idx += TMAIN) {
            int rr = idx >> 4, seg = idx & 15;
            cp16(smem_u32(sA + rr * CC + seg * 4),
                 (const char*)(node_mem + (((size_t)b * NB + (n0 + rr)) * TT + t) * CC) + seg * 16);
        }
    }
    asm volatile("cp.async.commit_group;");
    // prefetch pk/cnt chunk 0
    unsigned cur0 = 0xFFFFu, cur1 = 0xFFFFu; int cur_cnt = 0;
    if (wid < rows) {
        int nn = n0 + wid;
        cur_cnt = g_cnt2[nn * 2 + parity];
        const unsigned short* pkp = g_pk2 + (nn * 2 + parity) * MAXP;
        cur0 = pkp[lane];
        if (lane < 16) cur1 = pkp[lane + 32];
    }
    asm volatile("cp.async.wait_group 0;");
    __syncthreads();

    for (int c = 0; c < NCHUNK; c++) {
        // kick A stage for chunk c+1 (buffer (c+1)&1; prior readers done via last sync)
        int nic = rows - (c + 1) * NWMAIN;
        if (nic > NWMAIN) nic = NWMAIN;
        if (c + 1 < NCHUNK && nic > 0) {
            float* dst = sA + ((c + 1) & 1) * NWMAIN * CC;
            int base_n = n0 + (c + 1) * NWMAIN;
            for (int idx = threadIdx.x; idx < nic * 16; idx += TMAIN) {
                int rr = idx >> 4, seg = idx & 15;
                cp16(smem_u32(dst + rr * CC + seg * 4),
                     (const char*)(node_mem + (((size_t)b * NB + (base_n + rr)) * TT + t) * CC) + seg * 16);
            }
        }
        asm volatile("cp.async.commit_group;");
        // prefetch pk/cnt chunk c+1
        unsigned nxt0 = 0xFFFFu, nxt1 = 0xFFFFu; int nxt_cnt = 0;
        int nxt_i = (c + 1) * NWMAIN + wid;
        if (c + 1 < NCHUNK && nxt_i < rows) {
            int nn = n0 + nxt_i;
            nxt_cnt = g_cnt2[nn * 2 + parity];
            const unsigned short* pkp = g_pk2 + (nn * 2 + parity) * MAXP;
            nxt0 = pkp[lane];
            if (lane < 16) nxt1 = pkp[lane + 32];
        }

        // compute chunk c
        int myi = c * NWMAIN + wid;
        if (myi < rows) {
            int n = n0 + myi;
            const float4* ap = (const float4*)(sA + (c & 1) * NWMAIN * CC + wid * CC);
            bool h0 = lane < cur_cnt;
            bool h1 = (lane + 32) < cur_cnt;
            int r0 = cur0 & 1023, sw0 = r0 & 7;
            int r1 = cur1 & 1023, sw1 = r1 & 7;
            const uint4* ep0 = semb + (r0 << 3);
            const uint4* ep1 = semb + (r1 << 3);
            float d00 = 0, d01 = 0, d02 = 0, d03 = 0;
            float d10 = 0, d11 = 0, d12 = 0, d13 = 0;
            #pragma unroll
            for (int ph = 0; ph < 2; ph++) {
                float4 A[8];
                #pragma unroll
                for (int k = 0; k < 8; k++) A[k] = ap[ph * 8 + k];   // LDS broadcast
                #pragma unroll
                for (int wi = 0; wi < 4; wi++) {
                    int w = ph * 4 + wi;
                    float4 A0 = A[2 * wi], A1 = A[2 * wi + 1];
                    if (h0) {
                        uint4 q = ep0[w ^ sw0];
                        d00 = fmaf(A0.x, bf_lo(q.x), d00);
                        d01 = fmaf(A0.y, bf_hi(q.x), d01);
                        d02 = fmaf(A0.z, bf_lo(q.y), d02);
                        d03 = fmaf(A0.w, bf_hi(q.y), d03);
                        d00 = fmaf(A1.x, bf_lo(q.z), d00);
                        d01 = fmaf(A1.y, bf_hi(q.z), d01);
                        d02 = fmaf(A1.z, bf_lo(q.w), d02);
                        d03 = fmaf(A1.w, bf_hi(q.w), d03);
                    }
                    if (h1) {
                        uint4 q = ep1[w ^ sw1];
                        d10 = fmaf(A0.x, bf_lo(q.x), d10);
                        d11 = fmaf(A0.y, bf_hi(q.x), d11);
                        d12 = fmaf(A0.z, bf_lo(q.y), d12);
                        d13 = fmaf(A0.w, bf_hi(q.y), d13);
                        d10 = fmaf(A1.x, bf_lo(q.z), d10);
                        d11 = fmaf(A1.y, bf_hi(q.z), d11);
                        d12 = fmaf(A1.z, bf_lo(q.w), d12);
                        d13 = fmaf(A1.w, bf_hi(q.w), d13);
                    }
                }
            }
            float dot0 = (d00 + d01) + (d02 + d03);
            float dot1 = (d10 + d11) + (d12 + d13);
            float ex0 = h0 ? __expf(dot0 * 2.0f) : 0.0f;   // sim/TEMP, TEMP=0.5
            float ex1 = h1 ? __expf(dot1 * 2.0f) : 0.0f;
            float num = ((h0 && (cur0 & 2048)) ? ex0 : 0.0f)
                      + ((h1 && (cur1 & 2048)) ? ex1 : 0.0f);
            float den = ex0 + ex1
                      + ((h0 && (cur0 & 4096)) ? ex0 : 0.0f)
                      + ((h1 && (cur1 & 4096)) ? ex1 : 0.0f);
            #pragma unroll
            for (int off = 16; off; off >>= 1) {
                num += __shfl_xor_sync(0xffffffffu, num, off);
                den += __shfl_xor_sync(0xffffffffu, den, off);
            }
            if (lane == 0) {
                size_t o = ((size_t)parity * BT + bt) * NB + n;
                g_num[o] = num;
                g_den[o] = den;
            }
        }

        cur0 = nxt0; cur1 = nxt1; cur_cnt = nxt_cnt;
        asm volatile("cp.async.wait_group 0;");
        __syncthreads();
    }
}

// ---------------------------------------------------------------------------
// Kernel 3: combine parities, log, per-bt reduce; last block -> scalar loss.
// ---------------------------------------------------------------------------
__global__ void __launch_bounds__(320) k_post(float* __restrict__ out) {
    int bt = blockIdx.x;
    int tid = threadIdx.x;
    float v = 0.0f;
    if (tid < NB) {
        size_t o0 = (size_t)bt * NB + tid;
        size_t o1 = (size_t)(BT + bt) * NB + tid;
        float num = g_num[o0] + g_num[o1];
        float den = g_den[o0] + g_den[o1];
        v = __logf(num / (den + 1e-12f));
    }
    #pragma unroll
    for (int off = 16; off; off >>= 1)
        v += __shfl_xor_sync(0xffffffffu, v, off);
    __shared__ float wsum[10];
    __shared__ int s_last;
    if ((tid & 31) == 0) wsum[tid >> 5] = v;
    __syncthreads();
    if (tid == 0) {
        float s = 0.0f;
        #pragma unroll
        for (int k = 0; k < 10; k++) s += wsum[k];
        g_partial[bt] = s;
        __threadfence();
        int prev = atomicAdd(&g_done, 1);
        s_last = (prev == BT - 1) ? 1 : 0;
    }
    __syncthreads();
    if (s_last && tid == 0) {
        volatile float* gp = g_partial;
        float s = 0.0f;
        for (int k = 0; k < BT; k++) s += gp[k];
        out[0] = -s / (float)(BT * NB);
        g_done = 0;   // restore for next graph replay
    }
}

// ---------------------------------------------------------------------------
extern "C" void kernel_launch(void* const* d_in, const int* in_sizes, int n_in,
                              void* d_out, int out_size) {
    const float* node_memory = (const float*)d_in[0];   // [16,307,12,64]
    const float* subgraph    = (const float*)d_in[1];   // [16,307,12,64,4]
    const float* pos_mask    = (const float*)d_in[2];   // [307,1228]
    const float* neg_mask    = (const float*)d_in[3];   // [307,1228]
    float* out = (float*)d_out;

    cudaFuncSetAttribute(k_main, cudaFuncAttributeMaxDynamicSharedMemorySize,
                         SMEM_MAIN);

    // Kernel 1: normalize (2 groups/warp, 3684 blocks) + O(1)-dealt masks
    k_prep<<<NORM_BLOCKS + MASK_BLOCKS, 256>>>(subgraph, pos_mask, neg_mask);

    // Kernel 2: (bt, parity, half) units, 2 CTAs/SM, pipelined A staging
    k_main<<<NUNITS, TMAIN, SMEM_MAIN>>>(node_memory);

    // Kernel 3: combine + log + reduce -> scalar
    k_post<<<BT, 320>>>(out);
}

// round 10
// speedup vs baseline: 1.1173x; 1.1173x over previous
#include <cuda_runtime.h>
#include <cuda_bf16.h>

// Problem constants (fixed shapes from reference setup_inputs)
#define NB     307
#define SSUB   4
#define MTOT   (NB * SSUB)      // 1228 (even)
#define RHALF  614              // rows per parity slice
#define TT     12
#define BBAT   16
#define BT     (BBAT * TT)      // 192
#define CC     64
#define MAXE   64               // total entries per row (actual <= 44)
#define MAXP   48               // entries per (row,parity) (provably <= 42)
#define TMAIN  384
#define NWMAIN 12
#define SUBROWS 77              // A-stage sub-block
#define NUNITS (BT * 2 * 2)     // 768: (bt, parity, n-half)

#define EMB_B  (RHALF * CC * 2)        // 78,592
#define SA_B   (SUBROWS * CC * 4)      // 19,712
#define SMEM_MAIN (EMB_B + SA_B)       // 98,304 -> 2 CTAs/SM

#define NORM_BLOCKS 1842               // 58944 groups / 4 per warp / 8 warps
#define MASK_BLOCKS 39

// Scratch (static device allocations — no runtime alloc)
__device__ __nv_bfloat16 g_embT[(size_t)BT * 2 * RHALF * CC]; // [bt][par][r][c]
__device__ int           g_cnt2[NB * 2];
__device__ __align__(16) unsigned short g_pk2[NB * 2 * MAXP]; // r(10b)|pos<<11|dbl<<12
__device__ float         g_num[2 * BT * NB];                  // [par][bt][n]
__device__ float         g_den[2 * BT * NB];
__device__ float         g_partial[BT];
__device__ int           g_done;

__device__ __forceinline__ float bf_lo(unsigned u) { return __uint_as_float(u << 16); }
__device__ __forceinline__ float bf_hi(unsigned u) { return __uint_as_float(u & 0xffff0000u); }
__device__ __forceinline__ unsigned smem_u32(const void* p) {
    return (unsigned)__cvta_generic_to_shared(p);
}
__device__ __forceinline__ void cp16(unsigned dst, const void* src) {
    asm volatile("cp.async.cg.shared.global [%0], [%1], 16;" :: "r"(dst), "l"(src));
}

// ---------------------------------------------------------------------------
// Kernel 1: role A = normalize (4 groups per warp, MLP=8);
//           role B = masks with O(1) ballot-based bank dealing.
// ---------------------------------------------------------------------------
__global__ void __launch_bounds__(256) k_prep(const float* __restrict__ se,
                                              const float* __restrict__ pos,
                                              const float* __restrict__ neg) {
    if (blockIdx.x < NORM_BLOCKS) {
        int warp = (blockIdx.x * blockDim.x + threadIdx.x) >> 5;
        int lane = threadIdx.x & 31;
        // 4 (b,j,t) groups per warp: high MLP on the DRAM stream
        float4 va[4], vb[4];
        #pragma unroll
        for (int g = 0; g < 4; g++) {
            const float4* s = (const float4*)(se) + (size_t)(4 * warp + g) * CC;
            va[g] = s[2 * lane];
            vb[g] = s[2 * lane + 1];
        }
        #pragma unroll
        for (int g = 0; g < 4; g++) {
            float s0 = va[g].x * va[g].x + vb[g].x * vb[g].x;
            float s1 = va[g].y * va[g].y + vb[g].y * vb[g].y;
            float s2 = va[g].z * va[g].z + vb[g].z * vb[g].z;
            float s3 = va[g].w * va[g].w + vb[g].w * vb[g].w;
            #pragma unroll
            for (int off = 16; off; off >>= 1) {
                s0 += __shfl_xor_sync(0xffffffffu, s0, off);
                s1 += __shfl_xor_sync(0xffffffffu, s1, off);
                s2 += __shfl_xor_sync(0xffffffffu, s2, off);
                s3 += __shfl_xor_sync(0xffffffffu, s3, off);
            }
            float sc[4] = { rsqrtf(fmaxf(s0, 1e-24f)), rsqrtf(fmaxf(s1, 1e-24f)),
                            rsqrtf(fmaxf(s2, 1e-24f)), rsqrtf(fmaxf(s3, 1e-24f)) };
            float lo[4] = { va[g].x, va[g].y, va[g].z, va[g].w };
            float hi[4] = { vb[g].x, vb[g].y, vb[g].z, vb[g].w };

            int gid = 4 * warp + g;
            int t  = gid % TT;
            int bj = gid / TT;
            int j  = bj % NB;
            int bt = (bj / NB) * TT + t;
            #pragma unroll
            for (int s = 0; s < SSUB; s++) {
                int m = s * NB + j;
                __nv_bfloat162* dst = (__nv_bfloat162*)(g_embT
                    + (((size_t)(bt * 2 + (m & 1)) * RHALF + (m >> 1)) * CC)) + lane;
                *dst = __floats2bfloat162_rn(lo[s] * sc[s], hi[s] * sc[s]);
            }
        }
    } else {
        // mask role: warp w handles n = (blk-NORM)*8 + w
        __shared__ unsigned short buf[8][MAXE];   // r | pos<<11 | dbl<<12 | par<<13
        int mb = blockIdx.x - NORM_BLOCKS;
        int wid = threadIdx.x >> 5, lane = threadIdx.x & 31;
        if (mb == 0 && threadIdx.x == 0) g_done = 0;
        int n = mb * 8 + wid;
        if (n >= NB) return;
        int base = 0;
        for (int m0 = 0; m0 < MTOT; m0 += 32) {
            int m = m0 + lane;
            float p = 0.0f, q = 0.0f;
            if (m < MTOT) {
                p = pos[(size_t)n * MTOT + m];
                q = neg[(size_t)n * MTOT + m];
            }
            float w = p + q;
            unsigned bal = __ballot_sync(0xffffffffu, w > 0.0f);
            if (w > 0.0f) {
                int i = base + __popc(bal & ((1u << lane) - 1u));
                if (i < MAXE) {
                    buf[wid][i] = (unsigned short)((m >> 1)
                        | ((p > 0.5f) ? 2048 : 0)
                        | ((w > 1.5f) ? 4096 : 0)
                        | ((m & 1) << 13));
                }
            }
            base += __popc(bal);
        }
        int cnt = min(base, MAXE);
        __syncwarp();
        unsigned e0 = (lane < cnt)      ? buf[wid][lane]      : 0xFFFFu;
        unsigned e1 = (lane + 32 < cnt) ? buf[wid][lane + 32] : 0xFFFFu;
        unsigned below = (1u << lane) - 1u;

        #pragma unroll
        for (int par = 0; par < 2; par++) {
            bool v0 = (e0 != 0xFFFFu) && (((e0 >> 13) & 1) == (unsigned)par);
            bool v1 = (e1 != 0xFFFFu) && (((e1 >> 13) & 1) == (unsigned)par);
            int bk0 = e0 & 7, bk1 = e1 & 7;
            unsigned bal0[8], bal1[8];
            int cntb[8], cntp = 0;
            #pragma unroll
            for (int k = 0; k < 8; k++) {
                bal0[k] = __ballot_sync(0xffffffffu, v0 && bk0 == k);
                bal1[k] = __ballot_sync(0xffffffffu, v1 && bk1 == k);
                cntb[k] = __popc(bal0[k]) + __popc(bal1[k]);
                cntp += cntb[k];
            }
            // closed-form dealt position: pos = sum_b min(cntb[b], rk + (b<bk))
            if (v0) {
                int rk = __popc(bal0[bk0] & below);
                int ps = 0;
                #pragma unroll
                for (int b2 = 0; b2 < 8; b2++)
                    ps += min(cntb[b2], rk + (b2 < bk0 ? 1 : 0));
                g_pk2[(n * 2 + par) * MAXP + ps] = (unsigned short)(e0 & 0x1FFF);
            }
            if (v1) {
                int rk = __popc(bal0[bk1]) + __popc(bal1[bk1] & below);
                int ps = 0;
                #pragma unroll
                for (int b2 = 0; b2 < 8; b2++)
                    ps += min(cntb[b2], rk + (b2 < bk1 ? 1 : 0));
                g_pk2[(n * 2 + par) * MAXP + ps] = (unsigned short)(e1 & 0x1FFF);
            }
            if (lane == 0) g_cnt2[n * 2 + par] = min(cntp, MAXP);
        }
    }
}

// ---------------------------------------------------------------------------
// Kernel 2: main SDDMM. 768 blocks = (bt, parity, n-half), 2 CTAs/SM.
// Emb slice filled once per unit (swizzled). A-vectors staged in smem in two
// 77-row sub-blocks (ONE barrier between). pk/cnt prefetched one row ahead
// into regs. Hot loop: conflict-free LDS.128 (dealt order), 8 accumulators,
// guarded second-entry block (skipped when cnt<=32).
// ---------------------------------------------------------------------------
__global__ void __launch_bounds__(TMAIN, 2) k_main(const float* __restrict__ node_mem) {
    extern __shared__ __align__(16) char smraw[];
    uint4* semb = (uint4*)smraw;                 // RHALF*8 uint4, swizzled
    float* sA   = (float*)(smraw + EMB_B);       // 77 x 64 f32

    int u = blockIdx.x;
    int bt = u >> 2, parity = (u >> 1) & 1, half = u & 1;
    int b = bt / TT, t = bt % TT;
    int n0   = half ? 154 : 0;
    int rows = half ? 153 : 154;
    int wid = threadIdx.x >> 5, lane = threadIdx.x & 31;

    // emb fill (once per unit)
    {
        const uint4* esrc = (const uint4*)(g_embT) + (size_t)(bt * 2 + parity) * RHALF * 8;
        for (int idx = threadIdx.x; idx < RHALF * 8; idx += TMAIN) {
            int r = idx >> 3, w = idx & 7;
            cp16(smem_u32(&semb[(r << 3) | (w ^ (r & 7))]), esrc + idx);
        }
    }

    for (int sub = 0; sub < 2; sub++) {
        int rbase = sub * SUBROWS;
        int rs = rows - rbase;
        if (rs > SUBROWS) rs = SUBROWS;

        // stage A rows [rbase, rbase+rs)
        for (int idx = threadIdx.x; idx < rs * 16; idx += TMAIN) {
            int rr = idx >> 4, seg = idx & 15;
            cp16(smem_u32(sA + rr * CC + seg * 4),
                 (const char*)(node_mem
                    + (((size_t)b * NB + (n0 + rbase + rr)) * TT + t) * CC) + seg * 16);
        }
        asm volatile("cp.async.commit_group;");

        // prefetch pk/cnt for this warp's first row (overlaps the A stage)
        unsigned cur0 = 0xFFFFu, cur1 = 0xFFFFu; int ccnt = 0;
        if (wid < rs) {
            int idx2 = (n0 + rbase + wid) * 2 + parity;
            ccnt = g_cnt2[idx2];
            const unsigned short* pkp = g_pk2 + idx2 * MAXP;
            if (lane < ccnt)      cur0 = pkp[lane];
            if (lane + 32 < ccnt) cur1 = pkp[lane + 32];
        }
        asm volatile("cp.async.wait_group 0;");
        __syncthreads();

        for (int i = wid; i < rs; i += NWMAIN) {
            // prefetch next row's pk/cnt
            unsigned nx0 = 0xFFFFu, nx1 = 0xFFFFu; int ncnt = 0;
            if (i + NWMAIN < rs) {
                int idx2 = (n0 + rbase + i + NWMAIN) * 2 + parity;
                ncnt = g_cnt2[idx2];
                const unsigned short* pkp = g_pk2 + idx2 * MAXP;
                if (lane < ncnt)      nx0 = pkp[lane];
                if (lane + 32 < ncnt) nx1 = pkp[lane + 32];
            }

            bool h0 = cur0 != 0xFFFFu;
            bool h1 = cur1 != 0xFFFFu;
            int r0 = cur0 & 1023, sw0 = r0 & 7;
            int r1 = cur1 & 1023, sw1 = r1 & 7;
            const uint4* ep0 = semb + (r0 << 3);
            const uint4* ep1 = semb + (r1 << 3);
            const float4* ap = (const float4*)(sA + i * CC);
            float d00 = 0, d01 = 0, d02 = 0, d03 = 0;
            float d10 = 0, d11 = 0, d12 = 0, d13 = 0;
            #pragma unroll
            for (int ph = 0; ph < 2; ph++) {
                float4 A[8];
                #pragma unroll
                for (int k = 0; k < 8; k++) A[k] = ap[ph * 8 + k];   // LDS broadcast
                if (h0) {
                    #pragma unroll
                    for (int wi = 0; wi < 4; wi++) {
                        int w = ph * 4 + wi;
                        uint4 q = ep0[w ^ sw0];
                        float4 A0 = A[2 * wi], A1 = A[2 * wi + 1];
                        d00 = fmaf(A0.x, bf_lo(q.x), d00);
                        d01 = fmaf(A0.y, bf_hi(q.x), d01);
                        d02 = fmaf(A0.z, bf_lo(q.y), d02);
                        d03 = fmaf(A0.w, bf_hi(q.y), d03);
                        d00 = fmaf(A1.x, bf_lo(q.z), d00);
                        d01 = fmaf(A1.y, bf_hi(q.z), d01);
                        d02 = fmaf(A1.z, bf_lo(q.w), d02);
                        d03 = fmaf(A1.w, bf_hi(q.w), d03);
                    }
                }
                if (h1) {
                    #pragma unroll
                    for (int wi = 0; wi < 4; wi++) {
                        int w = ph * 4 + wi;
                        uint4 q = ep1[w ^ sw1];
                        float4 A0 = A[2 * wi], A1 = A[2 * wi + 1];
                        d10 = fmaf(A0.x, bf_lo(q.x), d10);
                        d11 = fmaf(A0.y, bf_hi(q.x), d11);
                        d12 = fmaf(A0.z, bf_lo(q.y), d12);
                        d13 = fmaf(A0.w, bf_hi(q.y), d13);
                        d10 = fmaf(A1.x, bf_lo(q.z), d10);
                        d11 = fmaf(A1.y, bf_hi(q.z), d11);
                        d12 = fmaf(A1.z, bf_lo(q.w), d12);
                        d13 = fmaf(A1.w, bf_hi(q.w), d13);
                    }
                }
            }
            float dot0 = (d00 + d01) + (d02 + d03);
            float dot1 = (d10 + d11) + (d12 + d13);
            float ex0 = h0 ? __expf(dot0 * 2.0f) : 0.0f;   // sim/TEMP, TEMP=0.5
            float ex1 = h1 ? __expf(dot1 * 2.0f) : 0.0f;
            float num = ((h0 && (cur0 & 2048)) ? ex0 : 0.0f)
                      + ((h1 && (cur1 & 2048)) ? ex1 : 0.0f);
            float den = ex0 + ex1
                      + ((h0 && (cur0 & 4096)) ? ex0 : 0.0f)
                      + ((h1 && (cur1 & 4096)) ? ex1 : 0.0f);
            #pragma unroll
            for (int off = 16; off; off >>= 1) {
                num += __shfl_xor_sync(0xffffffffu, num, off);
                den += __shfl_xor_sync(0xffffffffu, den, off);
            }
            if (lane == 0) {
                size_t o = ((size_t)parity * BT + bt) * NB + (n0 + rbase + i);
                g_num[o] = num;
                g_den[o] = den;
            }
            cur0 = nx0; cur1 = nx1; ccnt = ncnt;
        }
        if (sub == 0) __syncthreads();   // all readers done before restaging sA
    }
}

// ---------------------------------------------------------------------------
// Kernel 3: combine parities, log, per-bt reduce; last block -> scalar loss.
// ---------------------------------------------------------------------------
__global__ void __launch_bounds__(320) k_post(float* __restrict__ out) {
    int bt = blockIdx.x;
    int tid = threadIdx.x;
    float v = 0.0f;
    if (tid < NB) {
        size_t o0 = (size_t)bt * NB + tid;
        size_t o1 = (size_t)(BT + bt) * NB + tid;
        float num = g_num[o0] + g_num[o1];
        float den = g_den[o0] + g_den[o1];
        v = __logf(num / (den + 1e-12f));
    }
    #pragma unroll
    for (int off = 16; off; off >>= 1)
        v += __shfl_xor_sync(0xffffffffu, v, off);
    __shared__ float wsum[10];
    __shared__ int s_last;
    if ((tid & 31) == 0) wsum[tid >> 5] = v;
    __syncthreads();
    if (tid == 0) {
        float s = 0.0f;
        #pragma unroll
        for (int k = 0; k < 10; k++) s += wsum[k];
        g_partial[bt] = s;
        __threadfence();
        int prev = atomicAdd(&g_done, 1);
        s_last = (prev == BT - 1) ? 1 : 0;
    }
    __syncthreads();
    if (s_last && tid == 0) {
        volatile float* gp = g_partial;
        float s = 0.0f;
        for (int k = 0; k < BT; k++) s += gp[k];
        out[0] = -s / (float)(BT * NB);
        g_done = 0;   // restore for next graph replay
    }
}

// ---------------------------------------------------------------------------
extern "C" void kernel_launch(void* const* d_in, const int* in_sizes, int n_in,
                              void* d_out, int out_size) {
    const float* node_memory = (const float*)d_in[0];   // [16,307,12,64]
    const float* subgraph    = (const float*)d_in[1];   // [16,307,12,64,4]
    const float* pos_mask    = (const float*)d_in[2];   // [307,1228]
    const float* neg_mask    = (const float*)d_in[3];   // [307,1228]
    float* out = (float*)d_out;

    cudaFuncSetAttribute(k_main, cudaFuncAttributeMaxDynamicSharedMemorySize,
                         SMEM_MAIN);

    // Kernel 1: normalize (4 groups/warp, MLP 8) + O(1)-dealt masks
    k_prep<<<NORM_BLOCKS + MASK_BLOCKS, 256>>>(subgraph, pos_mask, neg_mask);

    // Kernel 2: (bt, parity, n-half) units, 2 CTAs/SM, 2-stage A staging
    k_main<<<NUNITS, TMAIN, SMEM_MAIN>>>(node_memory);

    // Kernel 3: combine + log + reduce -> scalar
    k_post<<<BT, 320>>>(out);
}